// round 15
// baseline (speedup 1.0000x reference)
#include <cuda_runtime.h>
#include <cuda_bf16.h>
#include <cstdint>

// RandomPooling: y[b,c,h,w] = x[b,c, refl(h+rh[b,h,w]-1), refl(w+rw[b,h,w]-1)]
// B=32, C=3, H=W=512, GAP=1 reflect padding.
// History:
//  R3  (PX=4):          39.1us, 6.0TB/s, 237MB DRAM
//  R7  (PX=8+hints):    49.5us — layout broke store/gather wavefront density
//  R9  (PX=4+cs hints): 38.6us, 5.75TB/s, 222MB DRAM  <- best
//  R10 (evict_last lit): ptxas rejects scalar .L2::evict_last on this toolchain
// R11: same retention idea via the supported path — createpolicy.fractional
//  .L2::evict_last + ld.global.nc.L2::cache_hint on the x gathers. x (100.7MB)
//  fits in L2 (126MB) and is re-read every graph replay; touch-once streams
//  (idx reads, out writes) stay evict-first. Target: ~167MB DRAM -> ~30us.

static constexpr int B = 32;
static constexpr int C = 3;
static constexpr int H = 512;
static constexpr int W = 512;
static constexpr int HW = H * W;          // 262144 = 1<<18
static constexpr int LOG_HW = 18;
static constexpr int LOG_W = 9;

__device__ __forceinline__ int refl(int s, int n) {
    // GAP=1: s in [-1, n]. reflect: -1 -> 1, n -> n-2.
    if (s < 0) s = -s;
    if (s >= n) s = 2 * n - 2 - s;
    return s;
}

// x gather load with an L2 evict-last access policy (retention descriptor).
__device__ __forceinline__ float ldg_el(const float* p, uint64_t pol) {
    float v;
    asm volatile("ld.global.nc.L2::cache_hint.f32 %0, [%1], %2;"
                 : "=f"(v) : "l"(p), "l"(pol));
    return v;
}

__global__ __launch_bounds__(256)
void random_pool_kernel(const float* __restrict__ x,
                        const int*   __restrict__ rh,
                        const int*   __restrict__ rw,
                        float*       __restrict__ out)
{
    // Each thread handles 4 consecutive w-pixels of one (b,h) row.
    // One float4 per thread -> warp store = 512B contiguous (full-density).
    int t = blockIdx.x * blockDim.x + threadIdx.x;
    int pix = t << 2;                      // first pixel index (b*HW + h*W + w)
    if (pix >= B * HW) return;

    // L2 policy: evict_last for 100% of accesses through this descriptor.
    uint64_t pol;
    asm volatile("createpolicy.fractional.L2::evict_last.b64 %0, 1.0;" : "=l"(pol));

    int b  = pix >> LOG_HW;
    int hw = pix & (HW - 1);
    int h  = hw >> LOG_W;
    int w  = hw & (W - 1);                 // multiple of 4

    // Touch-once index streams: evict-first in L2.
    int4 rh4 = __ldcs(reinterpret_cast<const int4*>(rh + pix));
    int4 rw4 = __ldcs(reinterpret_cast<const int4*>(rw + pix));

    // Source offsets within one channel plane (shared across all 3 channels)
    int sh0 = refl(h + rh4.x - 1, H);
    int sh1 = refl(h + rh4.y - 1, H);
    int sh2 = refl(h + rh4.z - 1, H);
    int sh3 = refl(h + rh4.w - 1, H);

    int sw0 = refl(w + 0 + rw4.x - 1, W);
    int sw1 = refl(w + 1 + rw4.y - 1, W);
    int sw2 = refl(w + 2 + rw4.z - 1, W);
    int sw3 = refl(w + 3 + rw4.w - 1, W);

    int src0 = (sh0 << LOG_W) + sw0;
    int src1 = (sh1 << LOG_W) + sw1;
    int src2 = (sh2 << LOG_W) + sw2;
    int src3 = (sh3 << LOG_W) + sw3;

    // Per-channel gather (evict-last policy) + coalesced streaming store.
    unsigned plane = (unsigned)(b * C) << LOG_HW;   // channel-0 plane offset
    #pragma unroll
    for (int c = 0; c < C; c++) {
        const float* __restrict__ xc = x + plane;
        float4 v;
        v.x = ldg_el(xc + src0, pol);
        v.y = ldg_el(xc + src1, pol);
        v.z = ldg_el(xc + src2, pol);
        v.w = ldg_el(xc + src3, pol);
        // Touch-once output: evict-first streaming store (512B/warp contiguous).
        __stcs(reinterpret_cast<float4*>(out + plane + hw), v);
        plane += HW;
    }
}

extern "C" void kernel_launch(void* const* d_in, const int* in_sizes, int n_in,
                              void* d_out, int out_size)
{
    const float* x  = (const float*)d_in[0];
    const int*   rh = (const int*)d_in[1];
    const int*   rw = (const int*)d_in[2];
    float*       y  = (float*)d_out;

    const int n_pix = B * HW;              // 8,388,608
    const int threads = 256;
    const int blocks = (n_pix / 4 + threads - 1) / threads;   // 8192
    random_pool_kernel<<<blocks, threads>>>(x, rh, rw, y);
}

// round 16
// speedup vs baseline: 1.1405x; 1.1405x over previous
#include <cuda_runtime.h>
#include <cuda_bf16.h>
#include <cstdint>

// RandomPooling: y[b,c,h,w] = x[b,c, refl(h+rh[b,h,w]-1), refl(w+rw[b,h,w]-1)]
// B=32, C=3, H=W=512, GAP=1 reflect padding.
// History:
//  R3  (PX=4):             39.1us, 6.0TB/s, 237MB DRAM
//  R7  (PX=8+hints):       49.5us — layout broke store/gather wavefront density
//  R9  (PX=4+cs hints):    38.6us, 5.75TB/s, 222MB DRAM  <- BEST
//  R10 (evict_last literal): ptxas reject (scalar form unsupported)
//  R15 (createpolicy+cache_hint): 48.3us, SAME 223MB traffic — retention not
//      honored across graph-replay launches, and the scalar cache_hint load
//      path costs extra L1tex throughput (L1 54->76%). Falsified; reverted.
// R16: revert to R9 verbatim — measured optimum. Traffic is at floor
// (167MB touch-once + ~55MB x after L2's natural reuse); remaining gap to
// peak BW is gather-grain / mixed-R-W turnaround, not addressable here.

static constexpr int B = 32;
static constexpr int C = 3;
static constexpr int H = 512;
static constexpr int W = 512;
static constexpr int HW = H * W;          // 262144 = 1<<18
static constexpr int LOG_HW = 18;
static constexpr int LOG_W = 9;

__device__ __forceinline__ int refl(int s, int n) {
    // GAP=1: s in [-1, n]. reflect: -1 -> 1, n -> n-2.
    if (s < 0) s = -s;
    if (s >= n) s = 2 * n - 2 - s;
    return s;
}

__global__ __launch_bounds__(256)
void random_pool_kernel(const float* __restrict__ x,
                        const int*   __restrict__ rh,
                        const int*   __restrict__ rw,
                        float*       __restrict__ out)
{
    // Each thread handles 4 consecutive w-pixels of one (b,h) row.
    // One float4 per thread -> warp store = 512B contiguous (full-density).
    int t = blockIdx.x * blockDim.x + threadIdx.x;
    int pix = t << 2;                      // first pixel index (b*HW + h*W + w)
    if (pix >= B * HW) return;

    int b  = pix >> LOG_HW;
    int hw = pix & (HW - 1);
    int h  = hw >> LOG_W;
    int w  = hw & (W - 1);                 // multiple of 4

    // Touch-once index streams: evict-first in L2.
    int4 rh4 = __ldcs(reinterpret_cast<const int4*>(rh + pix));
    int4 rw4 = __ldcs(reinterpret_cast<const int4*>(rw + pix));

    // Source offsets within one channel plane (shared across all 3 channels)
    int sh0 = refl(h + rh4.x - 1, H);
    int sh1 = refl(h + rh4.y - 1, H);
    int sh2 = refl(h + rh4.z - 1, H);
    int sh3 = refl(h + rh4.w - 1, H);

    int sw0 = refl(w + 0 + rw4.x - 1, W);
    int sw1 = refl(w + 1 + rw4.y - 1, W);
    int sw2 = refl(w + 2 + rw4.z - 1, W);
    int sw3 = refl(w + 3 + rw4.w - 1, W);

    int src0 = (sh0 << LOG_W) + sw0;
    int src1 = (sh1 << LOG_W) + sw1;
    int src2 = (sh2 << LOG_W) + sw2;
    int src3 = (sh3 << LOG_W) + sw3;

    // Per-channel gather (L1-cached __ldg) + coalesced streaming store.
    unsigned plane = (unsigned)(b * C) << LOG_HW;   // channel-0 plane offset
    #pragma unroll
    for (int c = 0; c < C; c++) {
        const float* __restrict__ xc = x + plane;
        float4 v;
        v.x = __ldg(xc + src0);
        v.y = __ldg(xc + src1);
        v.z = __ldg(xc + src2);
        v.w = __ldg(xc + src3);
        // Touch-once output: evict-first streaming store (512B/warp contiguous).
        __stcs(reinterpret_cast<float4*>(out + plane + hw), v);
        plane += HW;
    }
}

extern "C" void kernel_launch(void* const* d_in, const int* in_sizes, int n_in,
                              void* d_out, int out_size)
{
    const float* x  = (const float*)d_in[0];
    const int*   rh = (const int*)d_in[1];
    const int*   rw = (const int*)d_in[2];
    float*       y  = (float*)d_out;

    const int n_pix = B * HW;              // 8,388,608
    const int threads = 256;
    const int blocks = (n_pix / 4 + threads - 1) / threads;   // 8192
    random_pool_kernel<<<blocks, threads>>>(x, rh, rw, y);
}